// round 15
// baseline (speedup 1.0000x reference)
#include <cuda_runtime.h>
#include <cuda_bf16.h>
#include <cstdint>
#include <cstddef>

#define Bb 4
#define Hh 16
#define Ss 2048
#define Dd 64
#define QT 64
#define KT 64
#define NKT (Ss / KT)
#define NT 256

// ---- SMEM byte offsets ----
#define SM_QH 0                    // 64 x 64 bf16 -> 8 KB
#define SM_QL 8192
#define SM_BUF 16384               // two 32 KB buffers (KH 8K | KL 8K | VH 8K | VL 8K)
#define BUF_SZ 32768
#define OFF_KH 0
#define OFF_KL 8192
#define OFF_VH 16384
#define OFF_VL 24576
#define SM_RS (SM_BUF + 2 * BUF_SZ)   // 64 floats
#define SM_ORED SM_BUF                // reuse buffers for O reduction after loop
#define SMEM_BYTES (SM_RS + 512)

__device__ uint64_t g_mask_bits[(size_t)Ss * Ss / 64];   // 1 bit per (q,k)

// ================= fused prologue kernel =================
__global__ void mask_fused_kernel(const unsigned char* __restrict__ m) {
    __shared__ int i32bad, f32bad;
    const int tid = threadIdx.x;
    if (tid == 0) { i32bad = 0; f32bad = 0; }
    __syncthreads();
    for (int i = tid; i < 4096; i += 256) {
        unsigned char b = m[i];
        if ((i & 3) ? (b != 0) : (b > 1)) atomicOr(&i32bad, 1);
    }
    const unsigned int* md = reinterpret_cast<const unsigned int*>(m);
    for (int i = tid; i < 1024; i += 256) {
        unsigned int d = md[i];
        if (d != 0u && d != 0x3f800000u) atomicOr(&f32bad, 1);
    }
    __syncthreads();
    int sh, off;
    if (!i32bad)      { sh = 2; off = 0; }
    else if (!f32bad) { sh = 2; off = 3; }
    else              { sh = 0; off = 0; }

    const int i = blockIdx.x * blockDim.x + tid;
    if (i < Ss * Ss / 64) {
        uint64_t bits = 0;
        #pragma unroll 8
        for (int j = 0; j < 64; j++) {
            const size_t idx = (size_t)i * 64 + j;
            bits |= (uint64_t)(m[(idx << sh) + off] != 0) << j;
        }
        g_mask_bits[i] = bits;
    }
}

// ================= helpers =================
__device__ __forceinline__ uint32_t smem_u32(const void* p) {
    uint32_t a;
    asm("{ .reg .u64 t; cvta.to.shared.u64 t, %1; cvt.u32.u64 %0, t; }" : "=r"(a) : "l"(p));
    return a;
}
__device__ __forceinline__ uint32_t swz(uint32_t b) { return b ^ ((b >> 3) & 0x70); }
__device__ __forceinline__ uint32_t pb2(float lo, float hi) {
    uint32_t r;
    asm("cvt.rn.bf16x2.f32 %0, %1, %2;" : "=r"(r) : "f"(hi), "f"(lo));
    return r;
}
__device__ __forceinline__ float lo16f(uint32_t u) { return __uint_as_float(u << 16); }
__device__ __forceinline__ float hi16f(uint32_t u) { return __uint_as_float(u & 0xffff0000u); }

__device__ __forceinline__ void ldm4(uint32_t r[4], uint32_t a) {
    asm volatile("ldmatrix.sync.aligned.m8n8.x4.shared.b16 {%0,%1,%2,%3}, [%4];"
        : "=r"(r[0]), "=r"(r[1]), "=r"(r[2]), "=r"(r[3]) : "r"(a));
}
__device__ __forceinline__ void ldm4t(uint32_t r[4], uint32_t a) {
    asm volatile("ldmatrix.sync.aligned.m8n8.x4.trans.shared.b16 {%0,%1,%2,%3}, [%4];"
        : "=r"(r[0]), "=r"(r[1]), "=r"(r[2]), "=r"(r[3]) : "r"(a));
}
__device__ __forceinline__ void mma16816(float c[4], const uint32_t a[4],
                                         uint32_t b0, uint32_t b1) {
    asm volatile("mma.sync.aligned.m16n8k16.row.col.f32.bf16.bf16.f32 "
        "{%0,%1,%2,%3}, {%4,%5,%6,%7}, {%8,%9}, {%0,%1,%2,%3};"
        : "+f"(c[0]), "+f"(c[1]), "+f"(c[2]), "+f"(c[3])
        : "r"(a[0]), "r"(a[1]), "r"(a[2]), "r"(a[3]), "r"(b0), "r"(b1));
}

// convert one float4 to hi/lo bf16x2 pairs and store at swizzled offset
__device__ __forceinline__ void split_store(char* sm, uint32_t offH, uint32_t offL,
                                            uint32_t o, float4 f) {
    uint32_t h01 = pb2(f.x, f.y), h23 = pb2(f.z, f.w);
    *reinterpret_cast<uint2*>(sm + offH + o) = make_uint2(h01, h23);
    *reinterpret_cast<uint2*>(sm + offL + o) =
        make_uint2(pb2(f.x - lo16f(h01), f.y - hi16f(h01)),
                   pb2(f.z - lo16f(h23), f.w - hi16f(h23)));
}

// ================= main kernel =================
__global__ void __launch_bounds__(NT, 2)
attn_hmma_kernel(const float* __restrict__ Kg,
                 const float* __restrict__ Qg,
                 const float* __restrict__ Vg,
                 float* __restrict__ Og,
                 float* __restrict__ Wg)
{
    extern __shared__ char sm[];
    const uint32_t smb = smem_u32(sm);
    const int t = threadIdx.x;
    const int lane = t & 31;
    const int w = t >> 5;                  // warp 0..7
    const int bh = blockIdx.y;
    const int q0 = blockIdx.x * QT;

    const float* Qbh = Qg + (size_t)bh * Ss * Dd;
    const float* Kbh = Kg + (size_t)bh * Ss * Dd;
    const float* Vbh = Vg + (size_t)bh * Ss * Dd;

    float* rs = reinterpret_cast<float*>(sm + SM_RS);
    if (t < QT) rs[t] = 0.0f;

    // ---- load Q tile (64x64) -> bf16 hi/lo SMEM ----
    #pragma unroll
    for (int i = 0; i < 4; i++) {
        const int idx = t + NT * i;            // 0..1023
        const int row = idx >> 4;              // 0..63
        const int dc  = (idx & 15) * 4;
        float4 f = *reinterpret_cast<const float4*>(Qbh + (size_t)(q0 + row) * Dd + dc);
        split_store(sm, SM_QH, SM_QL, swz((uint32_t)(row * 128 + dc * 2)), f);
    }
    // ---- load K/V tile 0 into buffer 0 ----
    #pragma unroll
    for (int i = 0; i < 4; i++) {
        const int idx = t + NT * i;            // 0..1023
        const int row = idx >> 4;              // key row 0..63
        const int dc  = (idx & 15) * 4;
        const uint32_t o = swz((uint32_t)(row * 128 + dc * 2));
        float4 kf = *reinterpret_cast<const float4*>(Kbh + (size_t)row * Dd + dc);
        split_store(sm, SM_BUF + OFF_KH, SM_BUF + OFF_KL, o, kf);
        float4 vf = *reinterpret_cast<const float4*>(Vbh + (size_t)row * Dd + dc);
        split_store(sm, SM_BUF + OFF_VH, SM_BUF + OFF_VL, o, vf);
    }
    __syncthreads();

    // fragment lane decomposition
    const int gr = lane >> 2;
    const int cq = (lane & 3) * 2;
    const int arow = lane & 15;
    const int acolblk = lane >> 4;
    const int bn  = (lane & 7) + ((lane >> 4) << 3);
    const int bkh = ((lane >> 3) & 1) << 3;
    const int qh2 = w >> 1;                // q group (16 rows), 0..3
    const int kg  = w & 1;                 // 32-key slice, 0..1
    const int rA = 16 * qh2 + gr;
    const int rB = rA + 8;

    // ---- hoist Q fragments (invariant over k-tiles) ----
    uint32_t qhf[4][4], qlf[4][4];
    #pragma unroll
    for (int ks = 0; ks < 4; ks++) {
        const uint32_t ao = swz((uint32_t)((16 * qh2 + arow) * 128 +
                                           (ks * 16 + acolblk * 8) * 2));
        ldm4(qhf[ks], smb + SM_QH + ao);
        ldm4(qlf[ks], smb + SM_QL + ao);
    }

    float o_acc[8][4];
    #pragma unroll
    for (int nd = 0; nd < 8; nd++)
        o_acc[nd][0] = o_acc[nd][1] = o_acc[nd][2] = o_acc[nd][3] = 0.f;
    float rsumA = 0.f, rsumB = 0.f;

    float4 pk[4], pv[4];

    for (int kt = 0; kt < NKT; kt++) {
        const int kb0 = kt * KT;
        const uint32_t bufc = SM_BUF + (uint32_t)(kt & 1) * BUF_SZ;
        const uint32_t bufn = SM_BUF + (uint32_t)((kt + 1) & 1) * BUF_SZ;
        const bool pre = (kt + 1) < NKT;
        const int kb1 = kb0 + KT;

        // ---- issue K prefetch LDGs for tile kt+1 ----
        if (pre) {
            #pragma unroll
            for (int i = 0; i < 4; i++) {
                const int idx = t + NT * i;
                const int row = idx >> 4;
                const int dc  = (idx & 15) * 4;
                pk[i] = *reinterpret_cast<const float4*>(Kbh + (size_t)(kb1 + row) * Dd + dc);
            }
        }

        // ---- GEMM1: E[16 x 32] per warp = Qh*Kh + Qh*Kl + Ql*Kh ----
        float e[4][4];
        #pragma unroll
        for (int ng = 0; ng < 4; ng++)
            e[ng][0] = e[ng][1] = e[ng][2] = e[ng][3] = 0.f;
        #pragma unroll
        for (int ks = 0; ks < 4; ks++) {
            #pragma unroll
            for (int kb = 0; kb < 2; kb++) {
                const uint32_t bo = swz((uint32_t)((32 * kg + 16 * kb + bn) * 128 +
                                                   (ks * 16 + bkh) * 2));
                uint32_t khv[4], klv[4];
                ldm4(khv, smb + bufc + OFF_KH + bo);
                ldm4(klv, smb + bufc + OFF_KL + bo);
                mma16816(e[2 * kb + 0], qhf[ks], khv[0], khv[1]);
                mma16816(e[2 * kb + 1], qhf[ks], khv[2], khv[3]);
                mma16816(e[2 * kb + 0], qhf[ks], klv[0], klv[1]);
                mma16816(e[2 * kb + 1], qhf[ks], klv[2], klv[3]);
                mma16816(e[2 * kb + 0], qlf[ks], khv[0], khv[1]);
                mma16816(e[2 * kb + 1], qlf[ks], khv[2], khv[3]);
            }
        }

        // ---- store prefetched K into next buffer; issue V prefetch ----
        if (pre) {
            #pragma unroll
            for (int i = 0; i < 4; i++) {
                const int idx = t + NT * i;
                const int row = idx >> 4;
                const int dc  = (idx & 15) * 4;
                const uint32_t o = swz((uint32_t)(row * 128 + dc * 2));
                split_store(sm, bufn + OFF_KH, bufn + OFF_KL, o, pk[i]);
            }
            #pragma unroll
            for (int i = 0; i < 4; i++) {
                const int idx = t + NT * i;
                const int row = idx >> 4;
                const int dc  = (idx & 15) * 4;
                pv[i] = *reinterpret_cast<const float4*>(Vbh + (size_t)(kb1 + row) * Dd + dc);
            }
        }

        // ---- softmax in registers; bit-packed mask (1 variable shift/row) ----
        const uint64_t mAs = g_mask_bits[(size_t)(q0 + rA) * NKT + kt] >> (32 * kg + cq);
        const uint64_t mBs = g_mask_bits[(size_t)(q0 + rB) * NKT + kt] >> (32 * kg + cq);
        #pragma unroll
        for (int ng = 0; ng < 4; ng++) {
            const int gk = kb0 + 32 * kg + 8 * ng + cq;
            float p0 = ((mAs >> (8 * ng)) & 1)     ? 0.f : __expf(e[ng][0] * 0.125f);
            float p1 = ((mAs >> (8 * ng + 1)) & 1) ? 0.f : __expf(e[ng][1] * 0.125f);
            float p2 = ((mBs >> (8 * ng)) & 1)     ? 0.f : __expf(e[ng][2] * 0.125f);
            float p3 = ((mBs >> (8 * ng + 1)) & 1) ? 0.f : __expf(e[ng][3] * 0.125f);
            rsumA += p0 + p1;
            rsumB += p2 + p3;
            *reinterpret_cast<float2*>(Wg + ((size_t)bh * Ss + q0 + rA) * Ss + gk) =
                make_float2(p0, p1);
            *reinterpret_cast<float2*>(Wg + ((size_t)bh * Ss + q0 + rB) * Ss + gk) =
                make_float2(p2, p3);
            e[ng][0] = p0; e[ng][1] = p1; e[ng][2] = p2; e[ng][3] = p3;
        }

        // ---- GEMM2: O_partial[16 x 64] over this warp's 32 keys ----
        #pragma unroll
        for (int tc = 0; tc < 2; tc++) {
            uint32_t ah[4], al[4];
            #pragma unroll
            for (int half = 0; half < 2; half++) {
                const float* pvv = e[2 * tc + half];
                uint32_t h01 = pb2(pvv[0], pvv[1]);
                uint32_t h23 = pb2(pvv[2], pvv[3]);
                ah[2 * half + 0] = h01;
                ah[2 * half + 1] = h23;
                al[2 * half + 0] = pb2(pvv[0] - lo16f(h01), pvv[1] - hi16f(h01));
                al[2 * half + 1] = pb2(pvv[2] - lo16f(h23), pvv[3] - hi16f(h23));
            }
            const int kbase = 32 * kg + 16 * tc;
            #pragma unroll
            for (int ndp = 0; ndp < 4; ndp++) {
                const uint32_t vo = swz((uint32_t)(
                    (kbase + (lane & 7) + 8 * ((lane >> 3) & 1)) * 128 +
                    (16 * ndp + 8 * (lane >> 4)) * 2));
                uint32_t vh[4], vl[4];
                ldm4t(vh, smb + bufc + OFF_VH + vo);
                ldm4t(vl, smb + bufc + OFF_VL + vo);
                mma16816(o_acc[2 * ndp + 0], ah, vh[0], vh[1]);
                mma16816(o_acc[2 * ndp + 1], ah, vh[2], vh[3]);
                mma16816(o_acc[2 * ndp + 0], ah, vl[0], vl[1]);
                mma16816(o_acc[2 * ndp + 1], ah, vl[2], vl[3]);
                mma16816(o_acc[2 * ndp + 0], al, vh[0], vh[1]);
                mma16816(o_acc[2 * ndp + 1], al, vh[2], vh[3]);
            }
        }

        // ---- convert + store prefetched V into next buffer ----
        if (pre) {
            #pragma unroll
            for (int i = 0; i < 4; i++) {
                const int idx = t + NT * i;
                const int row = idx >> 4;
                const int dc  = (idx & 15) * 4;
                const uint32_t o = swz((uint32_t)(row * 128 + dc * 2));
                split_store(sm, bufn + OFF_VH, bufn + OFF_VL, o, pv[i]);
            }
        }
        __syncthreads();   // bufn written for kt+1; bufc reads complete
    }

    // ---- row-sum reduction ----
    atomicAdd(&rs[rA], rsumA);
    atomicAdd(&rs[rB], rsumB);

    // ---- O partial reduction: kg=1 stores, kg=0 combines ----
    if (kg == 1) {
        float* buf = reinterpret_cast<float*>(sm + SM_ORED) + qh2 * (16 * 68);
        #pragma unroll
        for (int nd = 0; nd < 8; nd++) {
            *reinterpret_cast<float2*>(buf + gr * 68 + 8 * nd + cq) =
                make_float2(o_acc[nd][0], o_acc[nd][1]);
            *reinterpret_cast<float2*>(buf + (gr + 8) * 68 + 8 * nd + cq) =
                make_float2(o_acc[nd][2], o_acc[nd][3]);
        }
    }
    __syncthreads();
    if (kg == 0) {
        const float* buf = reinterpret_cast<const float*>(sm + SM_ORED) + qh2 * (16 * 68);
        const float invA = 1.0f / rs[rA];
        const float invB = 1.0f / rs[rB];
        #pragma unroll
        for (int nd = 0; nd < 8; nd++) {
            float2 a = *reinterpret_cast<const float2*>(buf + gr * 68 + 8 * nd + cq);
            float2 b = *reinterpret_cast<const float2*>(buf + (gr + 8) * 68 + 8 * nd + cq);
            const int d0 = 8 * nd + cq;
            *reinterpret_cast<float2*>(Og + ((size_t)bh * Ss + q0 + rA) * Dd + d0) =
                make_float2((o_acc[nd][0] + a.x) * invA, (o_acc[nd][1] + a.y) * invA);
            *reinterpret_cast<float2*>(Og + ((size_t)bh * Ss + q0 + rB) * Dd + d0) =
                make_float2((o_acc[nd][2] + b.x) * invB, (o_acc[nd][3] + b.y) * invB);
        }
    }

    // ---- W rescale: re-read own 64x2048 block, normalize in place ----
    {
        const int row = t >> 2;                // 0..63
        const int c4  = t & 3;
        const float inv = 1.0f / rs[row];
        float* wd = Wg + ((size_t)bh * Ss + q0 + row) * Ss;
        #pragma unroll 8
        for (int j = 0; j < 128; j++) {
            const int c = (c4 + 4 * j) * 4;
            float4 v = *reinterpret_cast<const float4*>(wd + c);
            v.x *= inv; v.y *= inv; v.z *= inv; v.w *= inv;
            *reinterpret_cast<float4*>(wd + c) = v;
        }
    }
}

extern "C" void kernel_launch(void* const* d_in, const int* in_sizes, int n_in,
                              void* d_out, int out_size) {
    const int mask_elems = Ss * Ss;
    int mask_idx = -1;
    for (int i = 0; i < n_in; i++)
        if (in_sizes[i] == mask_elems) { mask_idx = i; break; }
    if (mask_idx < 0) mask_idx = 3;

    const float* kqv[3];
    int w = 0;
    for (int i = 0; i < n_in && w < 3; i++) {
        if (i == mask_idx) continue;
        kqv[w++] = (const float*)d_in[i];
    }
    const float* Kg = kqv[0];
    const float* Qg = kqv[1];
    const float* Vg = kqv[2];
    const unsigned char* Mg = (const unsigned char*)d_in[mask_idx];

    float* Og = (float*)d_out;
    float* Wg = (float*)d_out + (size_t)Bb * Hh * Ss * Dd;

    cudaFuncSetAttribute(attn_hmma_kernel,
                         cudaFuncAttributeMaxDynamicSharedMemorySize, SMEM_BYTES);

    mask_fused_kernel<<<(Ss * Ss / 64 + 255) / 256, 256>>>(Mg);

    dim3 grid(Ss / QT, Bb * Hh);
    attn_hmma_kernel<<<grid, NT, SMEM_BYTES>>>(Kg, Qg, Vg, Og, Wg);
}

// round 16
// speedup vs baseline: 1.2312x; 1.2312x over previous
#include <cuda_runtime.h>
#include <cuda_bf16.h>
#include <cstdint>
#include <cstddef>

#define Bb 4
#define Hh 16
#define Ss 2048
#define Dd 64
#define QT 64
#define KT 64
#define NKT (Ss / KT)
#define NT 256

// ---- SMEM byte offsets ----
#define SM_QH 0                    // 64 x 64 bf16 -> 8 KB
#define SM_QL 8192
#define SM_BUF 16384               // two 32 KB buffers (KH 8K | KL 8K | VH 8K | VL 8K)
#define BUF_SZ 32768
#define OFF_KH 0
#define OFF_KL 8192
#define OFF_VH 16384
#define OFF_VL 24576
#define SM_RS (SM_BUF + 2 * BUF_SZ)   // 64 floats
#define SM_ORED SM_BUF                // reuse buffers for O reduction after loop
#define SMEM_BYTES (SM_RS + 512)

__device__ uint64_t g_mask_bits[(size_t)Ss * Ss / 64];   // 1 bit per (q,k)

// ================= fused prologue kernel =================
__global__ void mask_fused_kernel(const unsigned char* __restrict__ m) {
    __shared__ int i32bad, f32bad;
    const int tid = threadIdx.x;
    if (tid == 0) { i32bad = 0; f32bad = 0; }
    __syncthreads();
    for (int i = tid; i < 4096; i += 256) {
        unsigned char b = m[i];
        if ((i & 3) ? (b != 0) : (b > 1)) atomicOr(&i32bad, 1);
    }
    const unsigned int* md = reinterpret_cast<const unsigned int*>(m);
    for (int i = tid; i < 1024; i += 256) {
        unsigned int d = md[i];
        if (d != 0u && d != 0x3f800000u) atomicOr(&f32bad, 1);
    }
    __syncthreads();
    int sh, off;
    if (!i32bad)      { sh = 2; off = 0; }
    else if (!f32bad) { sh = 2; off = 3; }
    else              { sh = 0; off = 0; }

    const int i = blockIdx.x * blockDim.x + tid;
    if (i < Ss * Ss / 64) {
        uint64_t bits = 0;
        #pragma unroll 8
        for (int j = 0; j < 64; j++) {
            const size_t idx = (size_t)i * 64 + j;
            bits |= (uint64_t)(m[(idx << sh) + off] != 0) << j;
        }
        g_mask_bits[i] = bits;
    }
}

// ================= helpers =================
__device__ __forceinline__ uint32_t smem_u32(const void* p) {
    uint32_t a;
    asm("{ .reg .u64 t; cvta.to.shared.u64 t, %1; cvt.u32.u64 %0, t; }" : "=r"(a) : "l"(p));
    return a;
}
__device__ __forceinline__ uint32_t swz(uint32_t b) { return b ^ ((b >> 3) & 0x70); }
__device__ __forceinline__ uint32_t pb2(float lo, float hi) {
    uint32_t r;
    asm("cvt.rn.bf16x2.f32 %0, %1, %2;" : "=r"(r) : "f"(hi), "f"(lo));
    return r;
}
__device__ __forceinline__ float lo16f(uint32_t u) { return __uint_as_float(u << 16); }
__device__ __forceinline__ float hi16f(uint32_t u) { return __uint_as_float(u & 0xffff0000u); }

__device__ __forceinline__ void ldm4(uint32_t r[4], uint32_t a) {
    asm volatile("ldmatrix.sync.aligned.m8n8.x4.shared.b16 {%0,%1,%2,%3}, [%4];"
        : "=r"(r[0]), "=r"(r[1]), "=r"(r[2]), "=r"(r[3]) : "r"(a));
}
__device__ __forceinline__ void ldm4t(uint32_t r[4], uint32_t a) {
    asm volatile("ldmatrix.sync.aligned.m8n8.x4.trans.shared.b16 {%0,%1,%2,%3}, [%4];"
        : "=r"(r[0]), "=r"(r[1]), "=r"(r[2]), "=r"(r[3]) : "r"(a));
}
__device__ __forceinline__ void mma16816(float c[4], const uint32_t a[4],
                                         uint32_t b0, uint32_t b1) {
    asm volatile("mma.sync.aligned.m16n8k16.row.col.f32.bf16.bf16.f32 "
        "{%0,%1,%2,%3}, {%4,%5,%6,%7}, {%8,%9}, {%0,%1,%2,%3};"
        : "+f"(c[0]), "+f"(c[1]), "+f"(c[2]), "+f"(c[3])
        : "r"(a[0]), "r"(a[1]), "r"(a[2]), "r"(a[3]), "r"(b0), "r"(b1));
}

// convert one float4 to hi/lo bf16x2 pairs and store at swizzled offset
__device__ __forceinline__ void split_store(char* sm, uint32_t offH, uint32_t offL,
                                            uint32_t o, float4 f) {
    uint32_t h01 = pb2(f.x, f.y), h23 = pb2(f.z, f.w);
    *reinterpret_cast<uint2*>(sm + offH + o) = make_uint2(h01, h23);
    *reinterpret_cast<uint2*>(sm + offL + o) =
        make_uint2(pb2(f.x - lo16f(h01), f.y - hi16f(h01)),
                   pb2(f.z - lo16f(h23), f.w - hi16f(h23)));
}

// ================= main kernel =================
__global__ void __launch_bounds__(NT, 2)
attn_hmma_kernel(const float* __restrict__ Kg,
                 const float* __restrict__ Qg,
                 const float* __restrict__ Vg,
                 float* __restrict__ Og,
                 float* __restrict__ Wg)
{
    extern __shared__ char sm[];
    const uint32_t smb = smem_u32(sm);
    const int t = threadIdx.x;
    const int lane = t & 31;
    const int w = t >> 5;                  // warp 0..7
    const int bh = blockIdx.y;
    const int q0 = blockIdx.x * QT;

    const float* Qbh = Qg + (size_t)bh * Ss * Dd;
    const float* Kbh = Kg + (size_t)bh * Ss * Dd;
    const float* Vbh = Vg + (size_t)bh * Ss * Dd;

    float* rs = reinterpret_cast<float*>(sm + SM_RS);
    if (t < QT) rs[t] = 0.0f;

    // ---- load Q tile (64x64) -> bf16 hi/lo SMEM ----
    #pragma unroll
    for (int i = 0; i < 4; i++) {
        const int idx = t + NT * i;            // 0..1023
        const int row = idx >> 4;              // 0..63
        const int dc  = (idx & 15) * 4;
        float4 f = *reinterpret_cast<const float4*>(Qbh + (size_t)(q0 + row) * Dd + dc);
        split_store(sm, SM_QH, SM_QL, swz((uint32_t)(row * 128 + dc * 2)), f);
    }
    // ---- load K/V tile 0 into buffer 0 ----
    #pragma unroll
    for (int i = 0; i < 4; i++) {
        const int idx = t + NT * i;            // 0..1023
        const int row = idx >> 4;              // key row 0..63
        const int dc  = (idx & 15) * 4;
        const uint32_t o = swz((uint32_t)(row * 128 + dc * 2));
        float4 kf = *reinterpret_cast<const float4*>(Kbh + (size_t)row * Dd + dc);
        split_store(sm, SM_BUF + OFF_KH, SM_BUF + OFF_KL, o, kf);
        float4 vf = *reinterpret_cast<const float4*>(Vbh + (size_t)row * Dd + dc);
        split_store(sm, SM_BUF + OFF_VH, SM_BUF + OFF_VL, o, vf);
    }
    __syncthreads();

    // fragment lane decomposition
    const int gr = lane >> 2;
    const int cq = (lane & 3) * 2;
    const int arow = lane & 15;
    const int acolblk = lane >> 4;
    const int bn  = (lane & 7) + ((lane >> 4) << 3);
    const int bkh = ((lane >> 3) & 1) << 3;
    const int qh2 = w >> 1;                // q group (16 rows), 0..3
    const int kg  = w & 1;                 // 32-key slice, 0..1
    const int rA = 16 * qh2 + gr;
    const int rB = rA + 8;

    float o_acc[8][4];
    #pragma unroll
    for (int nd = 0; nd < 8; nd++)
        o_acc[nd][0] = o_acc[nd][1] = o_acc[nd][2] = o_acc[nd][3] = 0.f;
    float rsumA = 0.f, rsumB = 0.f;

    float4 pk[4], pv[4];

    for (int kt = 0; kt < NKT; kt++) {
        const int kb0 = kt * KT;
        const uint32_t bufc = SM_BUF + (uint32_t)(kt & 1) * BUF_SZ;
        const uint32_t bufn = SM_BUF + (uint32_t)((kt + 1) & 1) * BUF_SZ;
        const bool pre = (kt + 1) < NKT;

        // ---- issue prefetch LDGs for tile kt+1 (consumed at tile end) ----
        if (pre) {
            const int kb1 = kb0 + KT;
            #pragma unroll
            for (int i = 0; i < 4; i++) {
                const int idx = t + NT * i;
                const int row = idx >> 4;
                const int dc  = (idx & 15) * 4;
                pk[i] = *reinterpret_cast<const float4*>(Kbh + (size_t)(kb1 + row) * Dd + dc);
                pv[i] = *reinterpret_cast<const float4*>(Vbh + (size_t)(kb1 + row) * Dd + dc);
            }
        }
        // ---- mask bits for this tile, pre-shifted (1 variable shift per row) ----
        const uint64_t mAs = g_mask_bits[(size_t)(q0 + rA) * NKT + kt] >> (32 * kg + cq);
        const uint64_t mBs = g_mask_bits[(size_t)(q0 + rB) * NKT + kt] >> (32 * kg + cq);

        // ---- GEMM1: E[16 x 32] per warp = Qh*Kh + Qh*Kl + Ql*Kh ----
        float e[4][4];
        #pragma unroll
        for (int ng = 0; ng < 4; ng++)
            e[ng][0] = e[ng][1] = e[ng][2] = e[ng][3] = 0.f;
        #pragma unroll
        for (int ks = 0; ks < 4; ks++) {
            const uint32_t ao = swz((uint32_t)((16 * qh2 + arow) * 128 +
                                               (ks * 16 + acolblk * 8) * 2));
            uint32_t qhf[4], qlf[4];
            ldm4(qhf, smb + SM_QH + ao);
            ldm4(qlf, smb + SM_QL + ao);
            #pragma unroll
            for (int kb = 0; kb < 2; kb++) {
                const uint32_t bo = swz((uint32_t)((32 * kg + 16 * kb + bn) * 128 +
                                                   (ks * 16 + bkh) * 2));
                uint32_t khv[4], klv[4];
                ldm4(khv, smb + bufc + OFF_KH + bo);
                ldm4(klv, smb + bufc + OFF_KL + bo);
                mma16816(e[2 * kb + 0], qhf, khv[0], khv[1]);
                mma16816(e[2 * kb + 1], qhf, khv[2], khv[3]);
                mma16816(e[2 * kb + 0], qhf, klv[0], klv[1]);
                mma16816(e[2 * kb + 1], qhf, klv[2], klv[3]);
                mma16816(e[2 * kb + 0], qlf, khv[0], khv[1]);
                mma16816(e[2 * kb + 1], qlf, khv[2], khv[3]);
            }
        }

        // ---- softmax in registers; constant-offset bit tests; stream unnorm W ----
        #pragma unroll
        for (int ng = 0; ng < 4; ng++) {
            const int gk = kb0 + 32 * kg + 8 * ng + cq;
            float p0 = ((mAs >> (8 * ng)) & 1)     ? 0.f : __expf(e[ng][0] * 0.125f);
            float p1 = ((mAs >> (8 * ng + 1)) & 1) ? 0.f : __expf(e[ng][1] * 0.125f);
            float p2 = ((mBs >> (8 * ng)) & 1)     ? 0.f : __expf(e[ng][2] * 0.125f);
            float p3 = ((mBs >> (8 * ng + 1)) & 1) ? 0.f : __expf(e[ng][3] * 0.125f);
            rsumA += p0 + p1;
            rsumB += p2 + p3;
            *reinterpret_cast<float2*>(Wg + ((size_t)bh * Ss + q0 + rA) * Ss + gk) =
                make_float2(p0, p1);
            *reinterpret_cast<float2*>(Wg + ((size_t)bh * Ss + q0 + rB) * Ss + gk) =
                make_float2(p2, p3);
            e[ng][0] = p0; e[ng][1] = p1; e[ng][2] = p2; e[ng][3] = p3;
        }

        // ---- GEMM2: O_partial[16 x 64] over this warp's 32 keys ----
        #pragma unroll
        for (int tc = 0; tc < 2; tc++) {
            uint32_t ah[4], al[4];
            #pragma unroll
            for (int half = 0; half < 2; half++) {
                const float* pvv = e[2 * tc + half];
                uint32_t h01 = pb2(pvv[0], pvv[1]);
                uint32_t h23 = pb2(pvv[2], pvv[3]);
                ah[2 * half + 0] = h01;
                ah[2 * half + 1] = h23;
                al[2 * half + 0] = pb2(pvv[0] - lo16f(h01), pvv[1] - hi16f(h01));
                al[2 * half + 1] = pb2(pvv[2] - lo16f(h23), pvv[3] - hi16f(h23));
            }
            const int kbase = 32 * kg + 16 * tc;
            #pragma unroll
            for (int ndp = 0; ndp < 4; ndp++) {
                const uint32_t vo = swz((uint32_t)(
                    (kbase + (lane & 7) + 8 * ((lane >> 3) & 1)) * 128 +
                    (16 * ndp + 8 * (lane >> 4)) * 2));
                uint32_t vh[4], vl[4];
                ldm4t(vh, smb + bufc + OFF_VH + vo);
                ldm4t(vl, smb + bufc + OFF_VL + vo);
                mma16816(o_acc[2 * ndp + 0], ah, vh[0], vh[1]);
                mma16816(o_acc[2 * ndp + 1], ah, vh[2], vh[3]);
                mma16816(o_acc[2 * ndp + 0], ah, vl[0], vl[1]);
                mma16816(o_acc[2 * ndp + 1], ah, vl[2], vl[3]);
                mma16816(o_acc[2 * ndp + 0], al, vh[0], vh[1]);
                mma16816(o_acc[2 * ndp + 1], al, vh[2], vh[3]);
            }
        }

        // ---- convert + store prefetched K/V into next buffer ----
        if (pre) {
            #pragma unroll
            for (int i = 0; i < 4; i++) {
                const int idx = t + NT * i;
                const int row = idx >> 4;
                const int dc  = (idx & 15) * 4;
                const uint32_t o = swz((uint32_t)(row * 128 + dc * 2));
                split_store(sm, bufn + OFF_KH, bufn + OFF_KL, o, pk[i]);
                split_store(sm, bufn + OFF_VH, bufn + OFF_VL, o, pv[i]);
            }
        }
        __syncthreads();   // bufn written for kt+1; bufc reads complete
    }

    // ---- row-sum reduction ----
    atomicAdd(&rs[rA], rsumA);
    atomicAdd(&rs[rB], rsumB);

    // ---- O partial reduction: kg=1 stores, kg=0 combines ----
    if (kg == 1) {
        float* buf = reinterpret_cast<float*>(sm + SM_ORED) + qh2 * (16 * 68);
        #pragma unroll
        for (int nd = 0; nd < 8; nd++) {
            *reinterpret_cast<float2*>(buf + gr * 68 + 8 * nd + cq) =
                make_float2(o_acc[nd][0], o_acc[nd][1]);
            *reinterpret_cast<float2*>(buf + (gr + 8) * 68 + 8 * nd + cq) =
                make_float2(o_acc[nd][2], o_acc[nd][3]);
        }
    }
    __syncthreads();
    if (kg == 0) {
        const float* buf = reinterpret_cast<const float*>(sm + SM_ORED) + qh2 * (16 * 68);
        const float invA = 1.0f / rs[rA];
        const float invB = 1.0f / rs[rB];
        #pragma unroll
        for (int nd = 0; nd < 8; nd++) {
            float2 a = *reinterpret_cast<const float2*>(buf + gr * 68 + 8 * nd + cq);
            float2 b = *reinterpret_cast<const float2*>(buf + (gr + 8) * 68 + 8 * nd + cq);
            const int d0 = 8 * nd + cq;
            *reinterpret_cast<float2*>(Og + ((size_t)bh * Ss + q0 + rA) * Dd + d0) =
                make_float2((o_acc[nd][0] + a.x) * invA, (o_acc[nd][1] + a.y) * invA);
            *reinterpret_cast<float2*>(Og + ((size_t)bh * Ss + q0 + rB) * Dd + d0) =
                make_float2((o_acc[nd][2] + b.x) * invB, (o_acc[nd][3] + b.y) * invB);
        }
    }

    // ---- W rescale: re-read own 64x2048 block, normalize in place ----
    {
        const int row = t >> 2;                // 0..63
        const int c4  = t & 3;
        const float inv = 1.0f / rs[row];
        float* wd = Wg + ((size_t)bh * Ss + q0 + row) * Ss;
        #pragma unroll 8
        for (int j = 0; j < 128; j++) {
            const int c = (c4 + 4 * j) * 4;
            float4 v = *reinterpret_cast<const float4*>(wd + c);
            v.x *= inv; v.y *= inv; v.z *= inv; v.w *= inv;
            *reinterpret_cast<float4*>(wd + c) = v;
        }
    }
}

extern "C" void kernel_launch(void* const* d_in, const int* in_sizes, int n_in,
                              void* d_out, int out_size) {
    const int mask_elems = Ss * Ss;
    int mask_idx = -1;
    for (int i = 0; i < n_in; i++)
        if (in_sizes[i] == mask_elems) { mask_idx = i; break; }
    if (mask_idx < 0) mask_idx = 3;

    const float* kqv[3];
    int w = 0;
    for (int i = 0; i < n_in && w < 3; i++) {
        if (i == mask_idx) continue;
        kqv[w++] = (const float*)d_in[i];
    }
    const float* Kg = kqv[0];
    const float* Qg = kqv[1];
    const float* Vg = kqv[2];
    const unsigned char* Mg = (const unsigned char*)d_in[mask_idx];

    float* Og = (float*)d_out;
    float* Wg = (float*)d_out + (size_t)Bb * Hh * Ss * Dd;

    cudaFuncSetAttribute(attn_hmma_kernel,
                         cudaFuncAttributeMaxDynamicSharedMemorySize, SMEM_BYTES);

    mask_fused_kernel<<<(Ss * Ss / 64 + 255) / 256, 256>>>(Mg);

    dim3 grid(Ss / QT, Bb * Hh);
    attn_hmma_kernel<<<grid, NT, SMEM_BYTES>>>(Kg, Qg, Vg, Og, Wg);
}

// round 17
// speedup vs baseline: 1.2677x; 1.0296x over previous
#include <cuda_runtime.h>
#include <cuda_bf16.h>
#include <cstdint>
#include <cstddef>

#define Bb 4
#define Hh 16
#define Ss 2048
#define Dd 64
#define QT 64
#define KT 64
#define NKT (Ss / KT)
#define NT 256

// ---- SMEM byte offsets ----
#define SM_QH 0                    // 64 x 64 bf16 -> 8 KB
#define SM_QL 8192
#define SM_BUF 16384               // two 32 KB buffers (KH 8K | KL 8K | VH 8K | VL 8K)
#define BUF_SZ 32768
#define OFF_KH 0
#define OFF_KL 8192
#define OFF_VH 16384
#define OFF_VL 24576
#define SM_RS (SM_BUF + 2 * BUF_SZ)   // 64 floats
#define SM_ORED SM_BUF                // reuse buffers for O reduction after loop
#define SMEM_BYTES (SM_RS + 512)

__device__ uint64_t g_mask_bits[(size_t)Ss * Ss / 64];   // 1 bit per (q,k)

// ================= fused prologue kernel =================
__global__ void mask_fused_kernel(const unsigned char* __restrict__ m) {
    __shared__ int i32bad, f32bad;
    const int tid = threadIdx.x;
    if (tid == 0) { i32bad = 0; f32bad = 0; }
    __syncthreads();
    for (int i = tid; i < 4096; i += 256) {
        unsigned char b = m[i];
        if ((i & 3) ? (b != 0) : (b > 1)) atomicOr(&i32bad, 1);
    }
    const unsigned int* md = reinterpret_cast<const unsigned int*>(m);
    for (int i = tid; i < 1024; i += 256) {
        unsigned int d = md[i];
        if (d != 0u && d != 0x3f800000u) atomicOr(&f32bad, 1);
    }
    __syncthreads();
    int sh, off;
    if (!i32bad)      { sh = 2; off = 0; }
    else if (!f32bad) { sh = 2; off = 3; }
    else              { sh = 0; off = 0; }

    const int i = blockIdx.x * blockDim.x + tid;
    if (i < Ss * Ss / 64) {
        uint64_t bits = 0;
        #pragma unroll 8
        for (int j = 0; j < 64; j++) {
            const size_t idx = (size_t)i * 64 + j;
            bits |= (uint64_t)(m[(idx << sh) + off] != 0) << j;
        }
        g_mask_bits[i] = bits;
    }
}

// ================= helpers =================
__device__ __forceinline__ uint32_t smem_u32(const void* p) {
    uint32_t a;
    asm("{ .reg .u64 t; cvta.to.shared.u64 t, %1; cvt.u32.u64 %0, t; }" : "=r"(a) : "l"(p));
    return a;
}
__device__ __forceinline__ uint32_t swz(uint32_t b) { return b ^ ((b >> 3) & 0x70); }
__device__ __forceinline__ uint32_t pb2(float lo, float hi) {
    uint32_t r;
    asm("cvt.rn.bf16x2.f32 %0, %1, %2;" : "=r"(r) : "f"(hi), "f"(lo));
    return r;
}
__device__ __forceinline__ float lo16f(uint32_t u) { return __uint_as_float(u << 16); }
__device__ __forceinline__ float hi16f(uint32_t u) { return __uint_as_float(u & 0xffff0000u); }

__device__ __forceinline__ void ldm4(uint32_t r[4], uint32_t a) {
    asm volatile("ldmatrix.sync.aligned.m8n8.x4.shared.b16 {%0,%1,%2,%3}, [%4];"
        : "=r"(r[0]), "=r"(r[1]), "=r"(r[2]), "=r"(r[3]) : "r"(a));
}
__device__ __forceinline__ void ldm4t(uint32_t r[4], uint32_t a) {
    asm volatile("ldmatrix.sync.aligned.m8n8.x4.trans.shared.b16 {%0,%1,%2,%3}, [%4];"
        : "=r"(r[0]), "=r"(r[1]), "=r"(r[2]), "=r"(r[3]) : "r"(a));
}
__device__ __forceinline__ void mma16816(float c[4], const uint32_t a[4],
                                         uint32_t b0, uint32_t b1) {
    asm volatile("mma.sync.aligned.m16n8k16.row.col.f32.bf16.bf16.f32 "
        "{%0,%1,%2,%3}, {%4,%5,%6,%7}, {%8,%9}, {%0,%1,%2,%3};"
        : "+f"(c[0]), "+f"(c[1]), "+f"(c[2]), "+f"(c[3])
        : "r"(a[0]), "r"(a[1]), "r"(a[2]), "r"(a[3]), "r"(b0), "r"(b1));
}

// convert one float4 to hi/lo bf16x2 pairs and store at swizzled offset
__device__ __forceinline__ void split_store(char* sm, uint32_t offH, uint32_t offL,
                                            uint32_t o, float4 f) {
    uint32_t h01 = pb2(f.x, f.y), h23 = pb2(f.z, f.w);
    *reinterpret_cast<uint2*>(sm + offH + o) = make_uint2(h01, h23);
    *reinterpret_cast<uint2*>(sm + offL + o) =
        make_uint2(pb2(f.x - lo16f(h01), f.y - hi16f(h01)),
                   pb2(f.z - lo16f(h23), f.w - hi16f(h23)));
}

// ================= main kernel =================
__global__ void __launch_bounds__(NT, 2)
attn_hmma_kernel(const float* __restrict__ Kg,
                 const float* __restrict__ Qg,
                 const float* __restrict__ Vg,
                 float* __restrict__ Og,
                 float* __restrict__ Wg)
{
    extern __shared__ char sm[];
    const uint32_t smb = smem_u32(sm);
    const int t = threadIdx.x;
    const int lane = t & 31;
    const int w = t >> 5;                  // warp 0..7
    const int bh = blockIdx.y;
    const int q0 = blockIdx.x * QT;

    const float* Qbh = Qg + (size_t)bh * Ss * Dd;
    const float* Kbh = Kg + (size_t)bh * Ss * Dd;
    const float* Vbh = Vg + (size_t)bh * Ss * Dd;

    float* rs = reinterpret_cast<float*>(sm + SM_RS);
    if (t < QT) rs[t] = 0.0f;

    // ---- load Q tile (64x64) -> bf16 hi/lo SMEM ----
    #pragma unroll
    for (int i = 0; i < 4; i++) {
        const int idx = t + NT * i;            // 0..1023
        const int row = idx >> 4;              // 0..63
        const int dc  = (idx & 15) * 4;
        float4 f = *reinterpret_cast<const float4*>(Qbh + (size_t)(q0 + row) * Dd + dc);
        split_store(sm, SM_QH, SM_QL, swz((uint32_t)(row * 128 + dc * 2)), f);
    }
    // ---- load K/V tile 0 into buffer 0 ----
    #pragma unroll
    for (int i = 0; i < 4; i++) {
        const int idx = t + NT * i;            // 0..1023
        const int row = idx >> 4;              // key row 0..63
        const int dc  = (idx & 15) * 4;
        const uint32_t o = swz((uint32_t)(row * 128 + dc * 2));
        float4 kf = *reinterpret_cast<const float4*>(Kbh + (size_t)row * Dd + dc);
        split_store(sm, SM_BUF + OFF_KH, SM_BUF + OFF_KL, o, kf);
        float4 vf = *reinterpret_cast<const float4*>(Vbh + (size_t)row * Dd + dc);
        split_store(sm, SM_BUF + OFF_VH, SM_BUF + OFF_VL, o, vf);
    }
    __syncthreads();

    // fragment lane decomposition
    const int gr = lane >> 2;
    const int cq = (lane & 3) * 2;
    const int arow = lane & 15;
    const int acolblk = lane >> 4;
    const int bn  = (lane & 7) + ((lane >> 4) << 3);
    const int bkh = ((lane >> 3) & 1) << 3;
    const int qh2 = w >> 1;                // q group (16 rows), 0..3
    const int kg  = w & 1;                 // 32-key slice, 0..1
    const int rA = 16 * qh2 + gr;
    const int rB = rA + 8;

    float o_acc[8][4];
    #pragma unroll
    for (int nd = 0; nd < 8; nd++)
        o_acc[nd][0] = o_acc[nd][1] = o_acc[nd][2] = o_acc[nd][3] = 0.f;
    float rsumA = 0.f, rsumB = 0.f;

    float4 pk[4], pv[4];

    for (int kt = 0; kt < NKT; kt++) {
        const int kb0 = kt * KT;
        const uint32_t bufc = SM_BUF + (uint32_t)(kt & 1) * BUF_SZ;
        const uint32_t bufn = SM_BUF + (uint32_t)((kt + 1) & 1) * BUF_SZ;
        const bool pre = (kt + 1) < NKT;

        // ---- issue prefetch LDGs for tile kt+1 (consumed at tile end) ----
        if (pre) {
            const int kb1 = kb0 + KT;
            #pragma unroll
            for (int i = 0; i < 4; i++) {
                const int idx = t + NT * i;
                const int row = idx >> 4;
                const int dc  = (idx & 15) * 4;
                pk[i] = *reinterpret_cast<const float4*>(Kbh + (size_t)(kb1 + row) * Dd + dc);
                pv[i] = *reinterpret_cast<const float4*>(Vbh + (size_t)(kb1 + row) * Dd + dc);
            }
        }
        // ---- mask bits for this tile, pre-shifted (1 variable shift per row) ----
        const uint64_t mAs = g_mask_bits[(size_t)(q0 + rA) * NKT + kt] >> (32 * kg + cq);
        const uint64_t mBs = g_mask_bits[(size_t)(q0 + rB) * NKT + kt] >> (32 * kg + cq);

        // ---- GEMM1: E[16 x 32] per warp = Qh*Kh + Qh*Kl + Ql*Kh ----
        float e[4][4];
        #pragma unroll
        for (int ng = 0; ng < 4; ng++)
            e[ng][0] = e[ng][1] = e[ng][2] = e[ng][3] = 0.f;
        #pragma unroll
        for (int ks = 0; ks < 4; ks++) {
            const uint32_t ao = swz((uint32_t)((16 * qh2 + arow) * 128 +
                                               (ks * 16 + acolblk * 8) * 2));
            uint32_t qhf[4], qlf[4];
            ldm4(qhf, smb + SM_QH + ao);
            ldm4(qlf, smb + SM_QL + ao);
            #pragma unroll
            for (int kb = 0; kb < 2; kb++) {
                const uint32_t bo = swz((uint32_t)((32 * kg + 16 * kb + bn) * 128 +
                                                   (ks * 16 + bkh) * 2));
                uint32_t khv[4], klv[4];
                ldm4(khv, smb + bufc + OFF_KH + bo);
                ldm4(klv, smb + bufc + OFF_KL + bo);
                mma16816(e[2 * kb + 0], qhf, khv[0], khv[1]);
                mma16816(e[2 * kb + 1], qhf, khv[2], khv[3]);
                mma16816(e[2 * kb + 0], qhf, klv[0], klv[1]);
                mma16816(e[2 * kb + 1], qhf, klv[2], klv[3]);
                mma16816(e[2 * kb + 0], qlf, khv[0], khv[1]);
                mma16816(e[2 * kb + 1], qlf, khv[2], khv[3]);
            }
        }

        // ---- softmax in registers; constant-offset bit tests; stream unnorm W ----
        #pragma unroll
        for (int ng = 0; ng < 4; ng++) {
            const int gk = kb0 + 32 * kg + 8 * ng + cq;
            float p0 = ((mAs >> (8 * ng)) & 1)     ? 0.f : __expf(e[ng][0] * 0.125f);
            float p1 = ((mAs >> (8 * ng + 1)) & 1) ? 0.f : __expf(e[ng][1] * 0.125f);
            float p2 = ((mBs >> (8 * ng)) & 1)     ? 0.f : __expf(e[ng][2] * 0.125f);
            float p3 = ((mBs >> (8 * ng + 1)) & 1) ? 0.f : __expf(e[ng][3] * 0.125f);
            rsumA += p0 + p1;
            rsumB += p2 + p3;
            *reinterpret_cast<float2*>(Wg + ((size_t)bh * Ss + q0 + rA) * Ss + gk) =
                make_float2(p0, p1);
            *reinterpret_cast<float2*>(Wg + ((size_t)bh * Ss + q0 + rB) * Ss + gk) =
                make_float2(p2, p3);
            e[ng][0] = p0; e[ng][1] = p1; e[ng][2] = p2; e[ng][3] = p3;
        }

        // ---- GEMM2: O_partial[16 x 64] over this warp's 32 keys ----
        #pragma unroll
        for (int tc = 0; tc < 2; tc++) {
            uint32_t ah[4], al[4];
            #pragma unroll
            for (int half = 0; half < 2; half++) {
                const float* pvv = e[2 * tc + half];
                uint32_t h01 = pb2(pvv[0], pvv[1]);
                uint32_t h23 = pb2(pvv[2], pvv[3]);
                ah[2 * half + 0] = h01;
                ah[2 * half + 1] = h23;
                al[2 * half + 0] = pb2(pvv[0] - lo16f(h01), pvv[1] - hi16f(h01));
                al[2 * half + 1] = pb2(pvv[2] - lo16f(h23), pvv[3] - hi16f(h23));
            }
            const int kbase = 32 * kg + 16 * tc;
            #pragma unroll
            for (int ndp = 0; ndp < 4; ndp++) {
                const uint32_t vo = swz((uint32_t)(
                    (kbase + (lane & 7) + 8 * ((lane >> 3) & 1)) * 128 +
                    (16 * ndp + 8 * (lane >> 4)) * 2));
                uint32_t vh[4], vl[4];
                ldm4t(vh, smb + bufc + OFF_VH + vo);
                ldm4t(vl, smb + bufc + OFF_VL + vo);
                mma16816(o_acc[2 * ndp + 0], ah, vh[0], vh[1]);
                mma16816(o_acc[2 * ndp + 1], ah, vh[2], vh[3]);
                mma16816(o_acc[2 * ndp + 0], ah, vl[0], vl[1]);
                mma16816(o_acc[2 * ndp + 1], ah, vl[2], vl[3]);
                mma16816(o_acc[2 * ndp + 0], al, vh[0], vh[1]);
                mma16816(o_acc[2 * ndp + 1], al, vh[2], vh[3]);
            }
        }

        // ---- convert + store prefetched K/V into next buffer ----
        if (pre) {
            #pragma unroll
            for (int i = 0; i < 4; i++) {
                const int idx = t + NT * i;
                const int row = idx >> 4;
                const int dc  = (idx & 15) * 4;
                const uint32_t o = swz((uint32_t)(row * 128 + dc * 2));
                split_store(sm, bufn + OFF_KH, bufn + OFF_KL, o, pk[i]);
                split_store(sm, bufn + OFF_VH, bufn + OFF_VL, o, pv[i]);
            }
        }
        __syncthreads();   // bufn written for kt+1; bufc reads complete
    }

    // ---- row-sum reduction ----
    atomicAdd(&rs[rA], rsumA);
    atomicAdd(&rs[rB], rsumB);

    // ---- O partial reduction: kg=1 stores, kg=0 combines ----
    if (kg == 1) {
        float* buf = reinterpret_cast<float*>(sm + SM_ORED) + qh2 * (16 * 68);
        #pragma unroll
        for (int nd = 0; nd < 8; nd++) {
            *reinterpret_cast<float2*>(buf + gr * 68 + 8 * nd + cq) =
                make_float2(o_acc[nd][0], o_acc[nd][1]);
            *reinterpret_cast<float2*>(buf + (gr + 8) * 68 + 8 * nd + cq) =
                make_float2(o_acc[nd][2], o_acc[nd][3]);
        }
    }
    __syncthreads();
    if (kg == 0) {
        const float* buf = reinterpret_cast<const float*>(sm + SM_ORED) + qh2 * (16 * 68);
        const float invA = 1.0f / rs[rA];
        const float invB = 1.0f / rs[rB];
        #pragma unroll
        for (int nd = 0; nd < 8; nd++) {
            float2 a = *reinterpret_cast<const float2*>(buf + gr * 68 + 8 * nd + cq);
            float2 b = *reinterpret_cast<const float2*>(buf + (gr + 8) * 68 + 8 * nd + cq);
            const int d0 = 8 * nd + cq;
            *reinterpret_cast<float2*>(Og + ((size_t)bh * Ss + q0 + rA) * Dd + d0) =
                make_float2((o_acc[nd][0] + a.x) * invA, (o_acc[nd][1] + a.y) * invA);
            *reinterpret_cast<float2*>(Og + ((size_t)bh * Ss + q0 + rB) * Dd + d0) =
                make_float2((o_acc[nd][2] + b.x) * invB, (o_acc[nd][3] + b.y) * invB);
        }
    }

    // ---- W rescale: newest-written columns FIRST (L2-hot), streaming hints ----
    {
        const int row = t >> 2;                // 0..63
        const int c4  = t & 3;
        const float inv = 1.0f / rs[row];
        float* wd = Wg + ((size_t)bh * Ss + q0 + row) * Ss;
        #pragma unroll 8
        for (int j = 127; j >= 0; j--) {
            const int c = (c4 + 4 * j) * 4;
            float4 v = __ldcs(reinterpret_cast<const float4*>(wd + c));
            v.x *= inv; v.y *= inv; v.z *= inv; v.w *= inv;
            __stcs(reinterpret_cast<float4*>(wd + c), v);
        }
    }
}

extern "C" void kernel_launch(void* const* d_in, const int* in_sizes, int n_in,
                              void* d_out, int out_size) {
    const int mask_elems = Ss * Ss;
    int mask_idx = -1;
    for (int i = 0; i < n_in; i++)
        if (in_sizes[i] == mask_elems) { mask_idx = i; break; }
    if (mask_idx < 0) mask_idx = 3;

    const float* kqv[3];
    int w = 0;
    for (int i = 0; i < n_in && w < 3; i++) {
        if (i == mask_idx) continue;
        kqv[w++] = (const float*)d_in[i];
    }
    const float* Kg = kqv[0];
    const float* Qg = kqv[1];
    const float* Vg = kqv[2];
    const unsigned char* Mg = (const unsigned char*)d_in[mask_idx];

    float* Og = (float*)d_out;
    float* Wg = (float*)d_out + (size_t)Bb * Hh * Ss * Dd;

    cudaFuncSetAttribute(attn_hmma_kernel,
                         cudaFuncAttributeMaxDynamicSharedMemorySize, SMEM_BYTES);

    mask_fused_kernel<<<(Ss * Ss / 64 + 255) / 256, 256>>>(Mg);

    dim3 grid(Ss / QT, Bb * Hh);
    attn_hmma_kernel<<<grid, NT, SMEM_BYTES>>>(Kg, Qg, Vg, Og, Wg);
}